// round 13
// baseline (speedup 1.0000x reference)
#include <cuda_runtime.h>
#include <cuda_bf16.h>

#define NGRAPH 1024
#define NNODE 360
#define NHEAD 8
#define DFEAT 256
#define NW (NNODE * NHEAD)    // 2880
#define WPT 45                // w elements per thread (2880/64)

typedef unsigned long long u64;

__device__ __forceinline__ u64 ffma2(u64 a, u64 b, u64 c) {
    u64 d;
    asm("fma.rn.f32x2 %0, %1, %2, %3;" : "=l"(d) : "l"(a), "l"(b), "l"(c));
    return d;
}
__device__ __forceinline__ u64 fmul2(u64 a, u64 b) {
    u64 d;
    asm("mul.rn.f32x2 %0, %1, %2;" : "=l"(d) : "l"(a), "l"(b));
    return d;
}
__device__ __forceinline__ ulonglong2 ldcs_u2(const ulonglong2* p) {
    ulonglong2 r;
    asm("ld.global.cs.v2.u64 {%0, %1}, [%2];"
        : "=l"(r.x), "=l"(r.y) : "l"(p));
    return r;
}

#define CROWS 6
#define NCHUNK 60

struct Chunk { ulonglong2 v[CROWS]; };

__device__ __forceinline__ void load_chunk(Chunk& ck, const ulonglong2* xp, int c) {
    #pragma unroll
    for (int j = 0; j < CROWS; ++j)
        ck.v[j] = ldcs_u2(xp + (size_t)(c * CROWS + j) * (DFEAT / 4));
}

__device__ __forceinline__ void compute_chunk(const Chunk& ck,
                                              const ulonglong2* s_attn, int c,
                                              u64* accA, u64* accB) {
    const int n0 = c * CROWS;
    #pragma unroll
    for (int j = 0; j < CROWS; ++j) {
        const ulonglong2 p0 = s_attn[(n0 + j) * 4 + 0];
        const ulonglong2 p1 = s_attn[(n0 + j) * 4 + 1];
        const ulonglong2 p2 = s_attn[(n0 + j) * 4 + 2];
        const ulonglong2 p3 = s_attn[(n0 + j) * 4 + 3];
        const u64 vx = ck.v[j].x, vy = ck.v[j].y;
        accA[0] = ffma2(vx, p0.x, accA[0]);  accB[0] = ffma2(vy, p0.x, accB[0]);
        accA[1] = ffma2(vx, p0.y, accA[1]);  accB[1] = ffma2(vy, p0.y, accB[1]);
        accA[2] = ffma2(vx, p1.x, accA[2]);  accB[2] = ffma2(vy, p1.x, accB[2]);
        accA[3] = ffma2(vx, p1.y, accA[3]);  accB[3] = ffma2(vy, p1.y, accB[3]);
        accA[4] = ffma2(vx, p2.x, accA[4]);  accB[4] = ffma2(vy, p2.x, accB[4]);
        accA[5] = ffma2(vx, p2.y, accA[5]);  accB[5] = ffma2(vy, p2.y, accB[5]);
        accA[6] = ffma2(vx, p3.x, accA[6]);  accB[6] = ffma2(vy, p3.x, accB[6]);
        accA[7] = ffma2(vx, p3.y, accA[7]);  accB[7] = ffma2(vy, p3.y, accB[7]);
    }
}

// ---------------------------------------------------------------------------
// Single fused kernel, grid 1024 (CTA = graph), 64 threads.
// Queue-order-aware prologue:
//   1. 45 batched w-LDGs FIRST (head of the per-SM L1tex FIFO, ~600cyc).
//   2. THEN issue x preload chunks 0,1 (their drain hides step 3/4).
//   3. exps from registers (thread t's 45 w values all belong to head t&7),
//      STS unnormalized dup(e,e) to s_attn, partial sum in-loop.
//   4. shfl.xor(8,16) + tiny smem combine -> s_inv2[h] = dup(1/sum_h).
//   5. R12's 3-deep / 6-row streaming pipeline on UNNORMALIZED weights.
//   6. Scale the 16 accumulators by s_inv2[h], store.
// ---------------------------------------------------------------------------
__global__ void __launch_bounds__(64, 7) fused_k(const float* __restrict__ x,
                                                 const float* __restrict__ w,
                                                 float* __restrict__ out) {
    __shared__ __align__(16) ulonglong2 s_attn[NNODE * 4];   // 23040 B
    __shared__ float s_ws[2][NHEAD];
    __shared__ u64 s_inv2[NHEAD];

    const int t = threadIdx.x;
    const int b = blockIdx.x;

    // (1) w loads FIRST: batched, ahead of all x traffic in the LSU queue
    float wv[WPT];
    #pragma unroll
    for (int k = 0; k < WPT; ++k)
        wv[k] = w[t + 64 * k];

    // (2) x preloads for chunks 0,1
    const ulonglong2* xp =
        (const ulonglong2*)x + (size_t)b * NNODE * (DFEAT / 4) + t;
    Chunk b0, b1, b2;
    load_chunk(b0, xp, 0);
    load_chunk(b1, xp, 1);

    // (3) exps + partial head sum (head h = t&7 for ALL this thread's values)
    u64* sa = (u64*)s_attn;                  // [NNODE][NHEAD] u64 view
    float psum = 0.f;
    #pragma unroll
    for (int k = 0; k < WPT; ++k) {
        float e = __expf(wv[k]);
        psum += e;
        unsigned int ei = __float_as_uint(e);
        sa[t + 64 * k] = (u64)ei | ((u64)ei << 32);
    }

    // (4) reduce within warp (lanes sharing t&7), then across the 2 warps
    psum += __shfl_xor_sync(0xFFFFFFFFu, psum, 8);
    psum += __shfl_xor_sync(0xFFFFFFFFu, psum, 16);
    if ((t & 31) < 8) s_ws[t >> 5][t & 7] = psum;
    __syncthreads();
    if (t < NHEAD) {
        float s = s_ws[0][t] + s_ws[1][t];
        unsigned int iv = __float_as_uint(1.f / s);
        s_inv2[t] = (u64)iv | ((u64)iv << 32);
    }
    __syncthreads();

    // (5) streaming pool, 3-deep pipeline, 60 chunks of 6 rows
    u64 accA[NHEAD], accB[NHEAD];
    #pragma unroll
    for (int h = 0; h < NHEAD; ++h) { accA[h] = 0ull; accB[h] = 0ull; }

    #pragma unroll 1
    for (int c = 0; c < NCHUNK - 6; c += 3) {
        load_chunk(b2, xp, c + 2);  compute_chunk(b0, s_attn, c,     accA, accB);
        load_chunk(b0, xp, c + 3);  compute_chunk(b1, s_attn, c + 1, accA, accB);
        load_chunk(b1, xp, c + 4);  compute_chunk(b2, s_attn, c + 2, accA, accB);
    }
    load_chunk(b2, xp, 56);  compute_chunk(b0, s_attn, 54, accA, accB);
    load_chunk(b0, xp, 57);  compute_chunk(b1, s_attn, 55, accA, accB);
    load_chunk(b1, xp, 58);  compute_chunk(b2, s_attn, 56, accA, accB);
    load_chunk(b2, xp, 59);  compute_chunk(b0, s_attn, 57, accA, accB);
    compute_chunk(b1, s_attn, 58, accA, accB);
    compute_chunk(b2, s_attn, 59, accA, accB);

    // (6) normalize accumulators, store
    ulonglong2* o = (ulonglong2*)out + (size_t)b * (NHEAD * DFEAT / 4) + t;
    #pragma unroll
    for (int h = 0; h < NHEAD; ++h) {
        const u64 iv = s_inv2[h];
        o[h * (DFEAT / 4)] =
            make_ulonglong2(fmul2(accA[h], iv), fmul2(accB[h], iv));
    }
}

extern "C" void kernel_launch(void* const* d_in, const int* in_sizes, int n_in,
                              void* d_out, int out_size) {
    const float* x = (const float*)d_in[0];   // [B*N, D] fp32
    // d_in[1] = batch (int64): exactly repeat(arange(B), N); layout only, unused
    const float* w = (const float*)d_in[2];   // [N, H] fp32
    float* out = (float*)d_out;               // [B, H*D] fp32

    fused_k<<<NGRAPH, 64>>>(x, w, out);
}

// round 15
// speedup vs baseline: 1.0227x; 1.0227x over previous
#include <cuda_runtime.h>
#include <cuda_bf16.h>

#define NGRAPH 1024
#define NNODE 360
#define NHEAD 8
#define DFEAT 256
#define NW (NNODE * NHEAD)    // 2880 floats = 720 float4

typedef unsigned long long u64;

__device__ __forceinline__ u64 ffma2(u64 a, u64 b, u64 c) {
    u64 d;
    asm("fma.rn.f32x2 %0, %1, %2, %3;" : "=l"(d) : "l"(a), "l"(b), "l"(c));
    return d;
}
__device__ __forceinline__ u64 fmul2(u64 a, u64 b) {
    u64 d;
    asm("mul.rn.f32x2 %0, %1, %2;" : "=l"(d) : "l"(a), "l"(b));
    return d;
}
__device__ __forceinline__ ulonglong2 ldcs_u2(const ulonglong2* p) {
    ulonglong2 r;
    asm("ld.global.cs.v2.u64 {%0, %1}, [%2];"
        : "=l"(r.x), "=l"(r.y) : "l"(p));
    return r;
}

#define CROWS 6
#define NCHUNK 60

struct Chunk { ulonglong2 v[CROWS]; };

__device__ __forceinline__ void load_chunk(Chunk& ck, const ulonglong2* xp, int c) {
    #pragma unroll
    for (int j = 0; j < CROWS; ++j)
        ck.v[j] = ldcs_u2(xp + (size_t)(c * CROWS + j) * (DFEAT / 4));
}

__device__ __forceinline__ void compute_chunk(const Chunk& ck,
                                              const ulonglong2* s_attn, int c,
                                              u64* accA, u64* accB) {
    const int n0 = c * CROWS;
    #pragma unroll
    for (int j = 0; j < CROWS; ++j) {
        const ulonglong2 p0 = s_attn[(n0 + j) * 4 + 0];
        const ulonglong2 p1 = s_attn[(n0 + j) * 4 + 1];
        const ulonglong2 p2 = s_attn[(n0 + j) * 4 + 2];
        const ulonglong2 p3 = s_attn[(n0 + j) * 4 + 3];
        const u64 vx = ck.v[j].x, vy = ck.v[j].y;
        accA[0] = ffma2(vx, p0.x, accA[0]);  accB[0] = ffma2(vy, p0.x, accB[0]);
        accA[1] = ffma2(vx, p0.y, accA[1]);  accB[1] = ffma2(vy, p0.y, accB[1]);
        accA[2] = ffma2(vx, p1.x, accA[2]);  accB[2] = ffma2(vy, p1.x, accB[2]);
        accA[3] = ffma2(vx, p1.y, accA[3]);  accB[3] = ffma2(vy, p1.y, accB[3]);
        accA[4] = ffma2(vx, p2.x, accA[4]);  accB[4] = ffma2(vy, p2.x, accB[4]);
        accA[5] = ffma2(vx, p2.y, accA[5]);  accB[5] = ffma2(vy, p2.y, accB[5]);
        accA[6] = ffma2(vx, p3.x, accA[6]);  accB[6] = ffma2(vy, p3.x, accB[6]);
        accA[7] = ffma2(vx, p3.y, accA[7]);  accB[7] = ffma2(vy, p3.y, accB[7]);
    }
}

// ---------------------------------------------------------------------------
// Single fused kernel, grid 1024 (CTA = graph), 64 threads. Spill-free
// prologue: w = 720 float4 -> 11 full strips (p = t+64k, k=0..10, p<=703)
// + tail strip p = 704+t for t<16. One float4 live at a time.
// Float j = 4p+m with p = t (mod 16) has head (4t+m)&7 -> 4 per-thread
// partial sums cover a fixed head quad; shfl.xor(2,4,8,16) reduce.
// Mainloop: R12's 3-deep / 6-row pipeline on UNNORMALIZED exp weights;
// the 16 accumulators are scaled by 1/sum at the end.
// ---------------------------------------------------------------------------
__global__ void __launch_bounds__(64, 7) fused_k(const float* __restrict__ x,
                                                 const float* __restrict__ w,
                                                 float* __restrict__ out) {
    __shared__ __align__(16) ulonglong2 s_attn[NNODE * 4];   // 23040 B
    __shared__ float s_ws[2][2][4];                           // [warp][parity][m]
    __shared__ u64 s_inv2[NHEAD];

    const int t = threadIdx.x;
    const int b = blockIdx.x;

    const float4* w4 = (const float4*)w;      // 720 float4
    const ulonglong2* xp =
        (const ulonglong2*)x + (size_t)b * NNODE * (DFEAT / 4) + t;

    // first w strip queued ahead of the x burst
    float4 wv = w4[t];

    // x preloads for chunks 0,1 (12 KB/CTA in flight)
    Chunk b0, b1, b2;
    load_chunk(b0, xp, 0);
    load_chunk(b1, xp, 1);

    // exp pass: 11 full strips + tail (t<16). Dup store to s_attn.
    uint4* sa4 = (uint4*)s_attn;              // 1440 uint4 (2 u64 each)
    float ps0 = 0.f, ps1 = 0.f, ps2 = 0.f, ps3 = 0.f;
    #pragma unroll 1
    for (int k = 0; k < 11; ++k) {
        const int p = t + 64 * k;             // <= 703
        float e0 = __expf(wv.x), e1 = __expf(wv.y);
        float e2 = __expf(wv.z), e3 = __expf(wv.w);
        if (k < 10) wv = w4[p + 64];                      // next full strip
        else if (t < 16) wv = w4[704 + t];                // tail strip
        ps0 += e0; ps1 += e1; ps2 += e2; ps3 += e3;
        unsigned int u0 = __float_as_uint(e0), u1 = __float_as_uint(e1);
        unsigned int u2 = __float_as_uint(e2), u3 = __float_as_uint(e3);
        sa4[p * 2 + 0] = make_uint4(u0, u0, u1, u1);
        sa4[p * 2 + 1] = make_uint4(u2, u2, u3, u3);
    }
    if (t < 16) {                              // tail: p = 704+t  (<= 719)
        const int p = 704 + t;
        float e0 = __expf(wv.x), e1 = __expf(wv.y);
        float e2 = __expf(wv.z), e3 = __expf(wv.w);
        ps0 += e0; ps1 += e1; ps2 += e2; ps3 += e3;
        unsigned int u0 = __float_as_uint(e0), u1 = __float_as_uint(e1);
        unsigned int u2 = __float_as_uint(e2), u3 = __float_as_uint(e3);
        sa4[p * 2 + 0] = make_uint4(u0, u0, u1, u1);
        sa4[p * 2 + 1] = make_uint4(u2, u2, u3, u3);
    }

    // reduce: head of ps_m is ((4t)&7)+m = ((t&1)*4)+m; parity class = t&1
    #pragma unroll
    for (int mask = 2; mask <= 16; mask <<= 1) {
        ps0 += __shfl_xor_sync(0xFFFFFFFFu, ps0, mask);
        ps1 += __shfl_xor_sync(0xFFFFFFFFu, ps1, mask);
        ps2 += __shfl_xor_sync(0xFFFFFFFFu, ps2, mask);
        ps3 += __shfl_xor_sync(0xFFFFFFFFu, ps3, mask);
    }
    if ((t & 31) < 2) {
        const int wp = t >> 5, par = t & 1;
        s_ws[wp][par][0] = ps0; s_ws[wp][par][1] = ps1;
        s_ws[wp][par][2] = ps2; s_ws[wp][par][3] = ps3;
    }
    __syncthreads();
    if (t < NHEAD) {
        const int par = t >> 2, m = t & 3;     // head t = par*4 + m
        float s = s_ws[0][par][m] + s_ws[1][par][m];
        unsigned int iv = __float_as_uint(1.f / s);
        s_inv2[t] = (u64)iv | ((u64)iv << 32);
    }
    __syncthreads();

    // streaming pool: 3-deep pipeline, 60 chunks of 6 rows (== R12)
    u64 accA[NHEAD], accB[NHEAD];
    #pragma unroll
    for (int h = 0; h < NHEAD; ++h) { accA[h] = 0ull; accB[h] = 0ull; }

    #pragma unroll 1
    for (int c = 0; c < NCHUNK - 6; c += 3) {
        load_chunk(b2, xp, c + 2);  compute_chunk(b0, s_attn, c,     accA, accB);
        load_chunk(b0, xp, c + 3);  compute_chunk(b1, s_attn, c + 1, accA, accB);
        load_chunk(b1, xp, c + 4);  compute_chunk(b2, s_attn, c + 2, accA, accB);
    }
    load_chunk(b2, xp, 56);  compute_chunk(b0, s_attn, 54, accA, accB);
    load_chunk(b0, xp, 57);  compute_chunk(b1, s_attn, 55, accA, accB);
    load_chunk(b1, xp, 58);  compute_chunk(b2, s_attn, 56, accA, accB);
    load_chunk(b2, xp, 59);  compute_chunk(b0, s_attn, 57, accA, accB);
    compute_chunk(b1, s_attn, 58, accA, accB);
    compute_chunk(b2, s_attn, 59, accA, accB);

    // normalize accumulators, store
    ulonglong2* o = (ulonglong2*)out + (size_t)b * (NHEAD * DFEAT / 4) + t;
    #pragma unroll
    for (int h = 0; h < NHEAD; ++h) {
        const u64 iv = s_inv2[h];
        o[h * (DFEAT / 4)] =
            make_ulonglong2(fmul2(accA[h], iv), fmul2(accB[h], iv));
    }
}

extern "C" void kernel_launch(void* const* d_in, const int* in_sizes, int n_in,
                              void* d_out, int out_size) {
    const float* x = (const float*)d_in[0];   // [B*N, D] fp32
    // d_in[1] = batch (int64): exactly repeat(arange(B), N); layout only, unused
    const float* w = (const float*)d_in[2];   // [N, H] fp32
    float* out = (float*)d_out;               // [B, H*D] fp32

    fused_k<<<NGRAPH, 64>>>(x, w, out);
}